// round 2
// baseline (speedup 1.0000x reference)
#include <cuda_runtime.h>
#include <cstdint>

#define Bq    4
#define Nq    2048
#define DINq  256
#define DOUTq 256
#define Hq    4
#define HDq   64
#define NEG_SLOPE 0.2f

// ---------------- scratch (no allocation allowed) ----------------
__device__ float g_h[Bq * Nq * DOUTq];       // 8 MB: h = x @ W^T
__device__ float g_ssrc[Bq * Nq * Hq];
__device__ float g_sdst[Bq * Nq * Hq];
__device__ float g_m[Bq * Nq * Hq];          // per-(row,head) softmax max
__device__ float g_linv[Bq * Nq * Hq];       // per-(row,head) 1/sum(exp)

// ---------------- packed f32x2 helpers ----------------
__device__ __forceinline__ void ffma2(unsigned long long& acc,
                                      unsigned long long p,
                                      unsigned long long h) {
    asm("fma.rn.f32x2 %0, %1, %2, %0;" : "+l"(acc) : "l"(p), "l"(h));
}
__device__ __forceinline__ unsigned long long pack2(float lo, float hi) {
    unsigned long long r;
    asm("mov.b64 %0, {%1, %2};" : "=l"(r) : "f"(lo), "f"(hi));
    return r;
}
__device__ __forceinline__ void unpack2(unsigned long long v, float& lo, float& hi) {
    asm("mov.b64 {%0, %1}, %2;" : "=f"(lo), "=f"(hi) : "l"(v));
}

// =====================================================================
// Kernel 1: h[row, d] = sum_k x[row, k] * W[d, k]
// 64x64 tile, 256 threads, 4x4 micro-tile, k-chunks of 16.
// =====================================================================
__global__ __launch_bounds__(256) void gemm_xWT_kernel(const float* __restrict__ x,
                                                       const float* __restrict__ W) {
    __shared__ float as[16][68];   // [k][row], padded
    __shared__ float bs[16][68];   // [k][col], padded

    const int tid = threadIdx.x;
    const int tx = tid & 15, ty = tid >> 4;
    const int row0 = blockIdx.x * 64;
    const int col0 = blockIdx.y * 64;

    float acc[4][4] = {};

    const int lr = tid >> 2;             // 0..63
    const int lq = (tid & 3) * 4;        // 0,4,8,12
    const float* xp = x + (size_t)(row0 + lr) * DINq + lq;
    const float* wp = W + (size_t)(col0 + lr) * DINq + lq;

    for (int kc = 0; kc < DINq; kc += 16) {
        float4 v  = *(const float4*)(xp + kc);
        float4 wv = *(const float4*)(wp + kc);
        as[lq + 0][lr] = v.x;  as[lq + 1][lr] = v.y;
        as[lq + 2][lr] = v.z;  as[lq + 3][lr] = v.w;
        bs[lq + 0][lr] = wv.x; bs[lq + 1][lr] = wv.y;
        bs[lq + 2][lr] = wv.z; bs[lq + 3][lr] = wv.w;
        __syncthreads();

#pragma unroll
        for (int k = 0; k < 16; k++) {
            float a4[4], b4[4];
            *(float4*)a4 = *(const float4*)&as[k][ty * 4];
            *(float4*)b4 = *(const float4*)&bs[k][tx * 4];
#pragma unroll
            for (int i = 0; i < 4; i++)
#pragma unroll
                for (int j = 0; j < 4; j++)
                    acc[i][j] += a4[i] * b4[j];
        }
        __syncthreads();
    }

#pragma unroll
    for (int i = 0; i < 4; i++) {
        float4 o;
        o.x = acc[i][0]; o.y = acc[i][1]; o.z = acc[i][2]; o.w = acc[i][3];
        *(float4*)&g_h[(size_t)(row0 + ty * 4 + i) * DOUTq + col0 + tx * 4] = o;
    }
}

// =====================================================================
// Kernel 2: s_src[row,h] = h[row, h*64: ] . a_src[h],  same for s_dst.
// One warp per (row, head) task. 8 warps per block.
// =====================================================================
__global__ __launch_bounds__(256) void score_kernel(const float* __restrict__ a_src,
                                                    const float* __restrict__ a_dst) {
    const int task = blockIdx.x * 8 + (threadIdx.x >> 5);   // row*4 + head
    const int ln = threadIdx.x & 31;
    const int row = task >> 2;
    const int head = task & 3;

    const float* hp = g_h + (size_t)row * DOUTq + head * HDq;
    float v0 = hp[ln], v1 = hp[ln + 32];
    float s1 = v0 * a_src[head * HDq + ln] + v1 * a_src[head * HDq + ln + 32];
    float s2 = v0 * a_dst[head * HDq + ln] + v1 * a_dst[head * HDq + ln + 32];
#pragma unroll
    for (int off = 16; off > 0; off >>= 1) {
        s1 += __shfl_xor_sync(0xFFFFFFFFu, s1, off);
        s2 += __shfl_xor_sync(0xFFFFFFFFu, s2, off);
    }
    if (ln == 0) {
        g_ssrc[task] = s1;
        g_sdst[task] = s2;
    }
}

// =====================================================================
// Kernel 3: softmax stats per (b, i, head): m = max_j e, linv = 1/sum exp(e-m)
// One block of 128 threads per row (b, i). Two passes over adj row (2nd from L1).
// =====================================================================
__global__ __launch_bounds__(128) void stats_kernel(const float* __restrict__ adj) {
    const int b = blockIdx.y;
    const int i = blockIdx.x;
    const int row = b * Nq + i;
    const float* arow = adj + (size_t)row * Nq;

    float4 ss4 = *(const float4*)&g_ssrc[row * 4];
    const float ss[4] = {ss4.x, ss4.y, ss4.z, ss4.w};

    float mloc[4] = {-1e30f, -1e30f, -1e30f, -1e30f};
    for (int j = threadIdx.x; j < Nq; j += 128) {
        float a = arow[j];
        if (a != 0.0f) {
            float4 sd = *(const float4*)&g_sdst[(b * Nq + j) * 4];
            float e0 = ss[0] + sd.x; e0 = e0 > 0.f ? e0 : NEG_SLOPE * e0;
            float e1 = ss[1] + sd.y; e1 = e1 > 0.f ? e1 : NEG_SLOPE * e1;
            float e2 = ss[2] + sd.z; e2 = e2 > 0.f ? e2 : NEG_SLOPE * e2;
            float e3 = ss[3] + sd.w; e3 = e3 > 0.f ? e3 : NEG_SLOPE * e3;
            mloc[0] = fmaxf(mloc[0], e0); mloc[1] = fmaxf(mloc[1], e1);
            mloc[2] = fmaxf(mloc[2], e2); mloc[3] = fmaxf(mloc[3], e3);
        }
    }
#pragma unroll
    for (int off = 16; off > 0; off >>= 1)
#pragma unroll
        for (int h = 0; h < 4; h++)
            mloc[h] = fmaxf(mloc[h], __shfl_xor_sync(0xFFFFFFFFu, mloc[h], off));

    __shared__ float red[4][4];
    const int w = threadIdx.x >> 5, ln = threadIdx.x & 31;
    if (ln == 0)
#pragma unroll
        for (int h = 0; h < 4; h++) red[h][w] = mloc[h];
    __syncthreads();

    float m[4];
#pragma unroll
    for (int h = 0; h < 4; h++)
        m[h] = fmaxf(fmaxf(red[h][0], red[h][1]), fmaxf(red[h][2], red[h][3]));
    __syncthreads();   // everyone read red before reuse

    float lloc[4] = {0.f, 0.f, 0.f, 0.f};
    for (int j = threadIdx.x; j < Nq; j += 128) {
        float a = arow[j];
        if (a != 0.0f) {
            float4 sd = *(const float4*)&g_sdst[(b * Nq + j) * 4];
            float e0 = ss[0] + sd.x; e0 = e0 > 0.f ? e0 : NEG_SLOPE * e0;
            float e1 = ss[1] + sd.y; e1 = e1 > 0.f ? e1 : NEG_SLOPE * e1;
            float e2 = ss[2] + sd.z; e2 = e2 > 0.f ? e2 : NEG_SLOPE * e2;
            float e3 = ss[3] + sd.w; e3 = e3 > 0.f ? e3 : NEG_SLOPE * e3;
            lloc[0] += __expf(e0 - m[0]); lloc[1] += __expf(e1 - m[1]);
            lloc[2] += __expf(e2 - m[2]); lloc[3] += __expf(e3 - m[3]);
        }
    }
#pragma unroll
    for (int off = 16; off > 0; off >>= 1)
#pragma unroll
        for (int h = 0; h < 4; h++)
            lloc[h] += __shfl_xor_sync(0xFFFFFFFFu, lloc[h], off);
    if (ln == 0)
#pragma unroll
        for (int h = 0; h < 4; h++) red[h][w] = lloc[h];
    __syncthreads();

    if (threadIdx.x == 0) {
#pragma unroll
        for (int h = 0; h < 4; h++) {
            float l = red[h][0] + red[h][1] + red[h][2] + red[h][3];
            g_m[row * 4 + h] = m[h];
            g_linv[row * 4 + h] = 1.0f / l;
        }
    }
}

// =====================================================================
// Kernel 4: fused aggregation.
//   out[b, i, d] = sum_j alpha[b,i,j,head(d)] * h[b, j, d]
// TI=16 rows of i, TJ=32 columns of j per tile. 256 threads; thread t owns
// output column d=t for all 16 i-rows, accumulated as 8 packed f32x2 regs.
// alpha tile computed into smem as p[jj][head][ti] (ti contiguous -> LDS.128).
// =====================================================================
#define TI 16
#define TJ 32

__global__ __launch_bounds__(256) void agg_kernel(const float* __restrict__ adj,
                                                  float* __restrict__ out) {
    __shared__ __align__(16) float sp[TJ * Hq * TI];   // p[jj][head][ti]  8 KB
    __shared__ float sadj[TI][TJ];                     // 2 KB
    __shared__ float ssd[TJ * Hq];                     // s_dst tile
    __shared__ float s_src_s[TI][Hq];
    __shared__ float s_m[TI][Hq];
    __shared__ float s_li[TI][Hq];

    const int t = threadIdx.x;
    const int head = t >> 6;
    const int b = blockIdx.y;
    const int i0 = blockIdx.x * TI;
    const int rowb = b * Nq + i0;

    if (t < TI) {
        float4 v;
        v = *(const float4*)&g_ssrc[(rowb + t) * 4];
        s_src_s[t][0] = v.x; s_src_s[t][1] = v.y; s_src_s[t][2] = v.z; s_src_s[t][3] = v.w;
        v = *(const float4*)&g_m[(rowb + t) * 4];
        s_m[t][0] = v.x; s_m[t][1] = v.y; s_m[t][2] = v.z; s_m[t][3] = v.w;
        v = *(const float4*)&g_linv[(rowb + t) * 4];
        s_li[t][0] = v.x; s_li[t][1] = v.y; s_li[t][2] = v.z; s_li[t][3] = v.w;
    }

    unsigned long long acc2[TI / 2];
#pragma unroll
    for (int q = 0; q < TI / 2; q++) acc2[q] = 0ull;   // bit pattern == (0.f, 0.f)

    const uint4* pbase = (const uint4*)(sp + head * TI);  // this head's ti-strip

    for (int jt = 0; jt < Nq / TJ; jt++) {
        const int j0 = jt * TJ;

        // ---- load adj tile (coalesced per i-row) + s_dst tile ----
#pragma unroll
        for (int r = 0; r < 2; r++) {
            int idx = t + r * 256;
            int ti = idx >> 5, jj = idx & 31;
            sadj[ti][jj] = adj[(size_t)(rowb + ti) * Nq + j0 + jj];
        }
        if (t < TJ * Hq) ssd[t] = g_sdst[(b * Nq + j0) * 4 + t];
        __syncthreads();

        // ---- compute p[jj][head][ti] = alpha ----
#pragma unroll
        for (int L = t; L < TJ * Hq * TI; L += 256) {
            int jj = L >> 6;
            int hh = (L >> 4) & 3;
            int ti = L & 15;
            float a = sadj[ti][jj];
            float p = 0.0f;
            if (a != 0.0f) {
                float e = s_src_s[ti][hh] + ssd[jj * 4 + hh];
                e = e > 0.f ? e : NEG_SLOPE * e;
                p = __expf(e - s_m[ti][hh]) * s_li[ti][hh];
            }
            sp[L] = p;
        }
        __syncthreads();

        // ---- rank-TJ update: acc[ti] += p[jj][head][ti] * h[j0+jj][t] ----
        const float* hrow = g_h + (size_t)(b * Nq + j0) * DOUTq + t;
#pragma unroll 8
        for (int jj = 0; jj < TJ; jj++) {
            float hv = __ldg(hrow + jj * DOUTq);
            unsigned long long h2 = pack2(hv, hv);
            const uint4* pp = pbase + jj * 16;   // 16 uint4 per jj across heads*ti
#pragma unroll
            for (int q = 0; q < 4; q++) {
                uint4 pv = pp[q];
                unsigned long long p01 = pack2(__uint_as_float(pv.x), __uint_as_float(pv.y));
                unsigned long long p23 = pack2(__uint_as_float(pv.z), __uint_as_float(pv.w));
                ffma2(acc2[q * 2 + 0], p01, h2);
                ffma2(acc2[q * 2 + 1], p23, h2);
            }
        }
        __syncthreads();
    }

    // ---- epilogue: acc2[q] holds i-rows (2q, 2q+1), column t ----
#pragma unroll
    for (int q = 0; q < TI / 2; q++) {
        float lo, hi;
        unpack2(acc2[q], lo, hi);
        out[(size_t)(rowb + 2 * q + 0) * DOUTq + t] = lo;
        out[(size_t)(rowb + 2 * q + 1) * DOUTq + t] = hi;
    }
}

// =====================================================================
extern "C" void kernel_launch(void* const* d_in, const int* in_sizes, int n_in,
                              void* d_out, int out_size) {
    const float* x     = (const float*)d_in[0];   // [B,N,DIN]
    const float* adj   = (const float*)d_in[1];   // [B,N,N]
    const float* W     = (const float*)d_in[2];   // [DOUT,DIN]
    const float* a_src = (const float*)d_in[3];   // [H,HD]
    const float* a_dst = (const float*)d_in[4];   // [H,HD]
    float* out = (float*)d_out;                   // [B,N,DOUT]

    gemm_xWT_kernel<<<dim3((Bq * Nq) / 64, DOUTq / 64), 256>>>(x, W);
    score_kernel<<<(Bq * Nq * Hq) / 8, 256>>>(a_src, a_dst);
    stats_kernel<<<dim3(Nq, Bq), 128>>>(adj);
    agg_kernel<<<dim3(Nq / TI, Bq), 256>>>(adj, out);
}